// round 13
// baseline (speedup 1.0000x reference)
#include <cuda_runtime.h>
#include <math.h>
#include <stdint.h>

// Problem constants
#define NN      16384
#define MMN     32
#define FF      256
#define ALPHA_L 0.2f

// ---------------- scratch ----------------
__device__ float g_O2[(size_t)NN * FF];   // output @ W2 (bias per node per out-feat)
// W1 rearranged: 32 blocks [s(8)][c(4)] of [n_local(64)][k_local(32) interleaved]
__device__ float g_Wt[(size_t)FF * FF];

// ---------------- helpers ----------------
__device__ __forceinline__ uint32_t f2tf32(float x) {
    uint32_t r;
    asm("cvt.rna.tf32.f32 %0, %1;" : "=r"(r) : "f"(x));
    return r;
}

__device__ __forceinline__ uint32_t smem_to_u32(const void* p) {
    uint32_t a;
    asm("{ .reg .u64 t; cvta.to.shared.u64 t, %1; cvt.u32.u64 %0, t; }"
        : "=r"(a) : "l"(p));
    return a;
}

__device__ __forceinline__ void cp_async16(uint32_t dst_smem, const void* src) {
    asm volatile("cp.async.cg.shared.global [%0], [%1], 16;"
                 :: "r"(dst_smem), "l"(src) : "memory");
}
__device__ __forceinline__ void cp_async_commit() {
    asm volatile("cp.async.commit_group;" ::: "memory");
}
template <int N>
__device__ __forceinline__ void cp_async_wait() {
    asm volatile("cp.async.wait_group %0;" :: "n"(N) : "memory");
}

__device__ __forceinline__ void mma_tf32(float c[4],
                                         float a0, float a1, float a2, float a3,
                                         float b0, float b1) {
    asm volatile(
        "mma.sync.aligned.m16n8k8.row.col.f32.tf32.tf32.f32 "
        "{%0,%1,%2,%3}, {%4,%5,%6,%7}, {%8,%9}, {%0,%1,%2,%3};\n"
        : "+f"(c[0]), "+f"(c[1]), "+f"(c[2]), "+f"(c[3])
        : "r"(__float_as_uint(a0)), "r"(__float_as_uint(a1)),
          "r"(__float_as_uint(a2)), "r"(__float_as_uint(a3)),
          "r"(__float_as_uint(b0)), "r"(__float_as_uint(b1)));
}

// ---------------------------------------------------------------------------
// Kernel 0: W1 -> g_Wt, tf32-rounded, [s(8)][c(4)][n(64)][k(32) interleaved]
// interleave within 8-block of k: k -> 2*(k&3) + ((k>>2)&1)
// ---------------------------------------------------------------------------
__global__ void wt_kernel(const float* __restrict__ W) {
    int n = blockIdx.x, k = threadIdx.x;
    int c = n >> 6, nl = n & 63;
    int s = k >> 5, kl = k & 31;
    int pos = (kl & ~7) + 2 * (kl & 3) + ((kl >> 2) & 1);
    size_t dst = ((size_t)((s * 4 + c) * 64 + nl)) * 32 + pos;
    g_Wt[dst] = __uint_as_float(f2tf32(W[(size_t)k * FF + n]));
}

// ---------------------------------------------------------------------------
// Kernel 1: O2 = output @ W2  (round-1 proven kernel, unchanged, 256 thr)
// ---------------------------------------------------------------------------
#define ROWS_PB   128
#define A_STRIDE1 260
#define W_STRIDE1 72

__global__ void __launch_bounds__(256, 1)
o2_gemm_kernel(const float* __restrict__ output, const float* __restrict__ W) {
    extern __shared__ float smemf[];
    float* As = smemf;
    float* Ws = As + ROWS_PB * A_STRIDE1;

    const int tid  = threadIdx.x;
    const int w    = tid >> 5;
    const int lane = tid & 31;
    const int g    = lane >> 2;
    const int tg   = lane & 3;
    const int mbase = w * 16;
    const int row0 = blockIdx.x * ROWS_PB;

    for (int idx = tid; idx < ROWS_PB * (FF / 4); idx += 256) {
        int r  = idx >> 6;
        int c4 = (idx & 63) * 4;
        float4 v = *(const float4*)(output + (size_t)(row0 + r) * FF + c4);
        float* d = &As[r * A_STRIDE1 + c4];
        d[0] = __uint_as_float(f2tf32(v.x));
        d[1] = __uint_as_float(f2tf32(v.y));
        d[2] = __uint_as_float(f2tf32(v.z));
        d[3] = __uint_as_float(f2tf32(v.w));
    }

    for (int nc = 0; nc < 4; nc++) {
        __syncthreads();
        for (int idx = tid; idx < FF * 16; idx += 256) {
            int k = idx >> 4;
            int j = (idx & 15) * 4;
            float4 v = *(const float4*)(W + (size_t)(FF + k) * FF + nc * 64 + j);
            float* d = &Ws[k * W_STRIDE1 + j];
            d[0] = __uint_as_float(f2tf32(v.x));
            d[1] = __uint_as_float(f2tf32(v.y));
            d[2] = __uint_as_float(f2tf32(v.z));
            d[3] = __uint_as_float(f2tf32(v.w));
        }
        __syncthreads();

        float c[8][4];
        #pragma unroll
        for (int n0 = 0; n0 < 8; n0++)
            #pragma unroll
            for (int i = 0; i < 4; i++) c[n0][i] = 0.f;

        #pragma unroll 4
        for (int k0 = 0; k0 < FF; k0 += 8) {
            float a0 = As[(mbase + g)     * A_STRIDE1 + k0 + tg];
            float a1 = As[(mbase + g + 8) * A_STRIDE1 + k0 + tg];
            float a2 = As[(mbase + g)     * A_STRIDE1 + k0 + tg + 4];
            float a3 = As[(mbase + g + 8) * A_STRIDE1 + k0 + tg + 4];
            #pragma unroll
            for (int n0 = 0; n0 < 8; n0++) {
                float b0 = Ws[(k0 + tg)     * W_STRIDE1 + n0 * 8 + g];
                float b1 = Ws[(k0 + tg + 4) * W_STRIDE1 + n0 * 8 + g];
                mma_tf32(c[n0], a0, a1, a2, a3, b0, b1);
            }
        }

        #pragma unroll
        for (int n0 = 0; n0 < 8; n0++) {
            int col = nc * 64 + n0 * 8 + tg * 2;
            size_t rA = (size_t)(row0 + mbase + g) * FF + col;
            size_t rB = (size_t)(row0 + mbase + g + 8) * FF + col;
            g_O2[rA]     = c[n0][0];
            g_O2[rA + 1] = c[n0][1];
            g_O2[rB]     = c[n0][2];
            g_O2[rB + 1] = c[n0][3];
        }
    }
}

// ---------------------------------------------------------------------------
// Kernel 2: fused GAT. 512 threads / 16 warps, warp grid 4m x 4chunk.
//   Warp (mw, nw) computes rows [mw*32,mw*32+32) x cols [nw*64,nw*64+64).
//   K staged in eighths of 32 for ALL 4 chunks, double-buffered cp.async.
//   Accumulators persist across all K -> single epilogue.
//   A smem: 128 x 260 fp32 (tf32-rounded), plain layout (proven).
//   B smem: 2 dbuf x [4 chunks][64 n][k 32+8 pad], k-pair interleaved.
// ---------------------------------------------------------------------------
#define THREADS2 512
#define A_ST 260
#define B_ST 40
#define A_BYTES    (128 * A_ST * 4)       // 133120
#define BBUF_FLOATS (4 * 64 * B_ST)       // 10240 floats
#define BBUF_BYTES (BBUF_FLOATS * 4)      // 40960
#define GAT_SMEM   (A_BYTES + 2 * BBUF_BYTES + 4 * FF * 4 + FF * 4 + 128 * 4 + 4 * 128 * 4)

__global__ void __launch_bounds__(THREADS2, 1)
gat_fused3_kernel(const float* __restrict__ transformed,
                  const float* __restrict__ a_vec,
                  float* __restrict__ out) {
    extern __shared__ char smem[];
    float* As    = (float*)smem;                               // 128 x 260
    float* Bs    = (float*)(smem + A_BYTES);                   // 2 x [4][64][40]
    float* o2_s  = (float*)(smem + A_BYTES + 2 * BBUF_BYTES);  // 4 x 256
    float* a_s   = o2_s + 4 * FF;                              // 256
    float* att_s = a_s + FF;                                   // 128
    float* e_sh  = att_s + 128;                                // 4 x 128

    const uint32_t bs_u = smem_to_u32(Bs);

    const int tid  = threadIdx.x;
    const int w    = tid >> 5;
    const int lane = tid & 31;
    const int g    = lane >> 2;
    const int tg   = lane & 3;
    const int mw   = w & 3;        // m-warp: rows [mw*32, mw*32+32) -> node mw
    const int nw   = w >> 2;       // chunk (cols [nw*64, nw*64+64))
    const int mbase = mw * 32;
    const int node0 = blockIdx.x * 4;

    // ---- B fill: stage s loads [s][c(4)][n(64)][32k] = 32KB contiguous ----
    auto fill_b = [&](int s) {
        const char* src = (const char*)g_Wt + (size_t)s * 32768;
        const uint32_t dst = bs_u + (uint32_t)(s & 1) * BBUF_BYTES;
        #pragma unroll
        for (int ii = 0; ii < 4; ii++) {
            int idx = tid + ii * THREADS2;          // 0..2047
            int r = idx >> 3, c16 = (idx & 7) * 16;
            cp_async16(dst + r * (B_ST * 4) + c16, src + r * 128 + c16);
        }
        cp_async_commit();
    };

    // ---- prefetch stages 0 and 1 ----
    fill_b(0);
    fill_b(1);

    // ---- A tile fill: plain layout, tf32-rounded (proven) ----
    const float* Asrc = transformed + (size_t)(node0 * MMN) * FF;
    for (int idx = tid; idx < 128 * 64; idx += THREADS2) {
        int r  = idx >> 6;
        int c4 = (idx & 63) * 4;
        float4 v = *(const float4*)(Asrc + (size_t)r * FF + c4);
        float* d = &As[r * A_ST + c4];
        d[0] = __uint_as_float(f2tf32(v.x));
        d[1] = __uint_as_float(f2tf32(v.y));
        d[2] = __uint_as_float(f2tf32(v.z));
        d[3] = __uint_as_float(f2tf32(v.w));
    }
    // ---- O2 bias + attention vector ----
    for (int idx = tid; idx < 4 * FF; idx += THREADS2)
        o2_s[idx] = g_O2[(size_t)(node0 + (idx >> 8)) * FF + (idx & 255)];
    if (tid < FF) a_s[tid] = a_vec[tid];

    float c[2][8][4];                      // 32m x 64n accumulators (full K)
    #pragma unroll
    for (int mt = 0; mt < 2; mt++)
        #pragma unroll
        for (int nt = 0; nt < 8; nt++)
            #pragma unroll
            for (int i = 0; i < 4; i++) c[mt][nt][i] = 0.f;

    for (int s = 0; s < 8; s++) {          // K eighths
        if (s == 7) cp_async_wait<0>(); else cp_async_wait<1>();
        __syncthreads();

        const float* Bq = Bs + (size_t)(s & 1) * BBUF_FLOATS + (size_t)nw * (64 * B_ST);
        const int kbase = s * 32;

        #pragma unroll
        for (int ko = 0; ko < 32; ko += 8) {
            const int k0 = kbase + ko;
            // A: 8 scalar LDS.32 (conflict-free, banks 4g+tg)
            float aA0 = As[(mbase + g)      * A_ST + k0 + tg];
            float aA4 = As[(mbase + g)      * A_ST + k0 + tg + 4];
            float aB0 = As[(mbase + g + 8)  * A_ST + k0 + tg];
            float aB4 = As[(mbase + g + 8)  * A_ST + k0 + tg + 4];
            float aC0 = As[(mbase + g + 16) * A_ST + k0 + tg];
            float aC4 = As[(mbase + g + 16) * A_ST + k0 + tg + 4];
            float aD0 = As[(mbase + g + 24) * A_ST + k0 + tg];
            float aD4 = As[(mbase + g + 24) * A_ST + k0 + tg + 4];

            #pragma unroll
            for (int nt = 0; nt < 8; nt++) {
                // B: LDS.64, interleaved pair (k0+tg, k0+tg+4) at index ko + 2tg
                float2 b = *(const float2*)&Bq[(nt * 8 + g) * B_ST + ko + 2 * tg];
                mma_tf32(c[0][nt], aA0, aB0, aA4, aB4, b.x, b.y);
                mma_tf32(c[1][nt], aC0, aD0, aC4, aD4, b.x, b.y);
            }
        }

        __syncthreads();   // all warps done reading this B buffer
        if (s < 6) fill_b(s + 2);
    }

    // ---- single epilogue: +bias, leaky-relu, dot with a -> e partials ----
    float ep[4] = {0.f, 0.f, 0.f, 0.f};   // rows mbase+{g,g+8,g+16,g+24}
    #pragma unroll
    for (int mt = 0; mt < 2; mt++) {
        #pragma unroll
        for (int nt = 0; nt < 8; nt++) {
            int o = nw * 64 + nt * 8 + 2 * tg;
            float o20 = o2_s[mw * FF + o];
            float o21 = o2_s[mw * FF + o + 1];
            float av0 = a_s[o];
            float av1 = a_s[o + 1];
            float y;
            y = c[mt][nt][0] + o20; y = (y > 0.f) ? y : ALPHA_L * y; ep[mt*2]   += y * av0;
            y = c[mt][nt][1] + o21; y = (y > 0.f) ? y : ALPHA_L * y; ep[mt*2]   += y * av1;
            y = c[mt][nt][2] + o20; y = (y > 0.f) ? y : ALPHA_L * y; ep[mt*2+1] += y * av0;
            y = c[mt][nt][3] + o21; y = (y > 0.f) ? y : ALPHA_L * y; ep[mt*2+1] += y * av1;
        }
    }

    // quad-reduce e partials, publish per chunk
    #pragma unroll
    for (int i = 0; i < 4; i++) {
        ep[i] += __shfl_down_sync(0xffffffffu, ep[i], 2, 4);
        ep[i] += __shfl_down_sync(0xffffffffu, ep[i], 1, 4);
    }
    if (tg == 0) {
        #pragma unroll
        for (int i = 0; i < 4; i++)
            e_sh[nw * 128 + mbase + i * 8 + g] = ep[i];
    }
    __syncthreads();

    // softmax per node (warps 0-3 handle nodes 0-3)
    if (w < 4) {
        float e = e_sh[w * 32 + lane] + e_sh[128 + w * 32 + lane]
                + e_sh[256 + w * 32 + lane] + e_sh[384 + w * 32 + lane];
        float mx = e;
        #pragma unroll
        for (int o = 16; o > 0; o >>= 1)
            mx = fmaxf(mx, __shfl_xor_sync(0xffffffffu, mx, o));
        float p = expf(e - mx);
        float sum = p;
        #pragma unroll
        for (int o = 16; o > 0; o >>= 1)
            sum += __shfl_xor_sync(0xffffffffu, sum, o);
        float att = p / sum;
        att_s[w * 32 + lane] = att;
        out[(size_t)NN * FF + (size_t)(node0 + w) * MMN + lane] = att;
    }
    __syncthreads();

    // h_prime[f] = sum_m att * A (plain smem layout), then ELU
    {
        const int f  = tid & 255;
        const int pr = tid >> 8;       // 0 or 1 -> nodes {0,1} / {2,3}
        #pragma unroll
        for (int t = 0; t < 2; t++) {
            const int nl = pr * 2 + t;
            float acc = 0.f;
            #pragma unroll 8
            for (int m = 0; m < MMN; m++) {
                int r = nl * MMN + m;
                acc = fmaf(att_s[r], As[r * A_ST + f], acc);
            }
            float rres = (acc > 0.f) ? acc : expm1f(acc);
            out[(size_t)(node0 + nl) * FF + f] = rres;
        }
    }
}

// ---------------------------------------------------------------------------
extern "C" void kernel_launch(void* const* d_in, const int* in_sizes, int n_in,
                              void* d_out, int out_size) {
    const float* transformed = (const float*)d_in[0];
    const float* output      = (const float*)d_in[1];
    const float* W           = (const float*)d_in[2];
    const float* a_vec       = (const float*)d_in[3];
    float* out = (float*)d_out;

    const int smem_o2 = (ROWS_PB * A_STRIDE1 + FF * W_STRIDE1) * sizeof(float);
    cudaFuncSetAttribute(o2_gemm_kernel,
                         cudaFuncAttributeMaxDynamicSharedMemorySize, smem_o2);
    cudaFuncSetAttribute(gat_fused3_kernel,
                         cudaFuncAttributeMaxDynamicSharedMemorySize, GAT_SMEM);

    wt_kernel<<<FF, FF>>>(W);
    o2_gemm_kernel<<<NN / ROWS_PB, 256, smem_o2>>>(output, W);
    gat_fused3_kernel<<<NN / 4, THREADS2, GAT_SMEM>>>(transformed, a_vec, out);
}

// round 14
// speedup vs baseline: 1.0004x; 1.0004x over previous
#include <cuda_runtime.h>
#include <math.h>
#include <stdint.h>

// Problem constants
#define NN      16384
#define MMN     32
#define FF      256
#define ALPHA_L 0.2f

// ---------------- scratch ----------------
__device__ float g_O2[(size_t)NN * FF];   // output @ W2 (bias per node per out-feat)
// W1 rearranged: 32 blocks [s(8)][c(4)] of [n_local(64)][k_local(32) interleaved]
__device__ float g_Wt[(size_t)FF * FF];

// ---------------- helpers ----------------
__device__ __forceinline__ uint32_t f2tf32(float x) {
    uint32_t r;
    asm("cvt.rna.tf32.f32 %0, %1;" : "=r"(r) : "f"(x));
    return r;
}

__device__ __forceinline__ uint32_t smem_to_u32(const void* p) {
    uint32_t a;
    asm("{ .reg .u64 t; cvta.to.shared.u64 t, %1; cvt.u32.u64 %0, t; }"
        : "=r"(a) : "l"(p));
    return a;
}

__device__ __forceinline__ void cp_async16(uint32_t dst_smem, const void* src) {
    asm volatile("cp.async.cg.shared.global [%0], [%1], 16;"
                 :: "r"(dst_smem), "l"(src) : "memory");
}
__device__ __forceinline__ void cp_async_commit() {
    asm volatile("cp.async.commit_group;" ::: "memory");
}
template <int N>
__device__ __forceinline__ void cp_async_wait() {
    asm volatile("cp.async.wait_group %0;" :: "n"(N) : "memory");
}

__device__ __forceinline__ void mma_tf32(float c[4],
                                         float a0, float a1, float a2, float a3,
                                         float b0, float b1) {
    asm volatile(
        "mma.sync.aligned.m16n8k8.row.col.f32.tf32.tf32.f32 "
        "{%0,%1,%2,%3}, {%4,%5,%6,%7}, {%8,%9}, {%0,%1,%2,%3};\n"
        : "+f"(c[0]), "+f"(c[1]), "+f"(c[2]), "+f"(c[3])
        : "r"(__float_as_uint(a0)), "r"(__float_as_uint(a1)),
          "r"(__float_as_uint(a2)), "r"(__float_as_uint(a3)),
          "r"(__float_as_uint(b0)), "r"(__float_as_uint(b1)));
}

// ---------------------------------------------------------------------------
// Kernel 0: W1 -> g_Wt, tf32-rounded, [s(8)][c(4)][n(64)][k(32) interleaved]
// interleave within 8-block of k: k -> 2*(k&3) + ((k>>2)&1)
// ---------------------------------------------------------------------------
__global__ void wt_kernel(const float* __restrict__ W) {
    int n = blockIdx.x, k = threadIdx.x;
    int c = n >> 6, nl = n & 63;
    int s = k >> 5, kl = k & 31;
    int pos = (kl & ~7) + 2 * (kl & 3) + ((kl >> 2) & 1);
    size_t dst = ((size_t)((s * 4 + c) * 64 + nl)) * 32 + pos;
    g_Wt[dst] = __uint_as_float(f2tf32(W[(size_t)k * FF + n]));
}

// ---------------------------------------------------------------------------
// Kernel 1: O2 = output @ W2  (round-1 proven kernel, unchanged, 256 thr)
// ---------------------------------------------------------------------------
#define ROWS_PB   128
#define A_STRIDE1 260
#define W_STRIDE1 72

__global__ void __launch_bounds__(256, 1)
o2_gemm_kernel(const float* __restrict__ output, const float* __restrict__ W) {
    extern __shared__ float smemf[];
    float* As = smemf;
    float* Ws = As + ROWS_PB * A_STRIDE1;

    const int tid  = threadIdx.x;
    const int w    = tid >> 5;
    const int lane = tid & 31;
    const int g    = lane >> 2;
    const int tg   = lane & 3;
    const int mbase = w * 16;
    const int row0 = blockIdx.x * ROWS_PB;

    for (int idx = tid; idx < ROWS_PB * (FF / 4); idx += 256) {
        int r  = idx >> 6;
        int c4 = (idx & 63) * 4;
        float4 v = *(const float4*)(output + (size_t)(row0 + r) * FF + c4);
        float* d = &As[r * A_STRIDE1 + c4];
        d[0] = __uint_as_float(f2tf32(v.x));
        d[1] = __uint_as_float(f2tf32(v.y));
        d[2] = __uint_as_float(f2tf32(v.z));
        d[3] = __uint_as_float(f2tf32(v.w));
    }

    for (int nc = 0; nc < 4; nc++) {
        __syncthreads();
        for (int idx = tid; idx < FF * 16; idx += 256) {
            int k = idx >> 4;
            int j = (idx & 15) * 4;
            float4 v = *(const float4*)(W + (size_t)(FF + k) * FF + nc * 64 + j);
            float* d = &Ws[k * W_STRIDE1 + j];
            d[0] = __uint_as_float(f2tf32(v.x));
            d[1] = __uint_as_float(f2tf32(v.y));
            d[2] = __uint_as_float(f2tf32(v.z));
            d[3] = __uint_as_float(f2tf32(v.w));
        }
        __syncthreads();

        float c[8][4];
        #pragma unroll
        for (int n0 = 0; n0 < 8; n0++)
            #pragma unroll
            for (int i = 0; i < 4; i++) c[n0][i] = 0.f;

        #pragma unroll 4
        for (int k0 = 0; k0 < FF; k0 += 8) {
            float a0 = As[(mbase + g)     * A_STRIDE1 + k0 + tg];
            float a1 = As[(mbase + g + 8) * A_STRIDE1 + k0 + tg];
            float a2 = As[(mbase + g)     * A_STRIDE1 + k0 + tg + 4];
            float a3 = As[(mbase + g + 8) * A_STRIDE1 + k0 + tg + 4];
            #pragma unroll
            for (int n0 = 0; n0 < 8; n0++) {
                float b0 = Ws[(k0 + tg)     * W_STRIDE1 + n0 * 8 + g];
                float b1 = Ws[(k0 + tg + 4) * W_STRIDE1 + n0 * 8 + g];
                mma_tf32(c[n0], a0, a1, a2, a3, b0, b1);
            }
        }

        #pragma unroll
        for (int n0 = 0; n0 < 8; n0++) {
            int col = nc * 64 + n0 * 8 + tg * 2;
            size_t rA = (size_t)(row0 + mbase + g) * FF + col;
            size_t rB = (size_t)(row0 + mbase + g + 8) * FF + col;
            g_O2[rA]     = c[n0][0];
            g_O2[rA + 1] = c[n0][1];
            g_O2[rB]     = c[n0][2];
            g_O2[rB + 1] = c[n0][3];
        }
    }
}

// ---------------------------------------------------------------------------
// Kernel 2: fused GAT. 512 threads / 16 warps, warp grid 4m x 4chunk.
//   Warp (mw, nw) computes rows [mw*32,mw*32+32) x cols [nw*64,nw*64+64).
//   K staged in eighths of 32 for ALL 4 chunks, double-buffered cp.async.
//   Accumulators persist across all K -> single epilogue.
//   A smem: 128 x 260 fp32 (tf32-rounded), plain layout (proven).
//   B smem: 2 dbuf x [4 chunks][64 n][k 32+8 pad], k-pair interleaved.
// ---------------------------------------------------------------------------
#define THREADS2 512
#define A_ST 260
#define B_ST 40
#define A_BYTES    (128 * A_ST * 4)       // 133120
#define BBUF_FLOATS (4 * 64 * B_ST)       // 10240 floats
#define BBUF_BYTES (BBUF_FLOATS * 4)      // 40960
#define GAT_SMEM   (A_BYTES + 2 * BBUF_BYTES + 4 * FF * 4 + FF * 4 + 128 * 4 + 4 * 128 * 4)

__global__ void __launch_bounds__(THREADS2, 1)
gat_fused3_kernel(const float* __restrict__ transformed,
                  const float* __restrict__ a_vec,
                  float* __restrict__ out) {
    extern __shared__ char smem[];
    float* As    = (float*)smem;                               // 128 x 260
    float* Bs    = (float*)(smem + A_BYTES);                   // 2 x [4][64][40]
    float* o2_s  = (float*)(smem + A_BYTES + 2 * BBUF_BYTES);  // 4 x 256
    float* a_s   = o2_s + 4 * FF;                              // 256
    float* att_s = a_s + FF;                                   // 128
    float* e_sh  = att_s + 128;                                // 4 x 128

    const uint32_t bs_u = smem_to_u32(Bs);

    const int tid  = threadIdx.x;
    const int w    = tid >> 5;
    const int lane = tid & 31;
    const int g    = lane >> 2;
    const int tg   = lane & 3;
    const int mw   = w & 3;        // m-warp: rows [mw*32, mw*32+32) -> node mw
    const int nw   = w >> 2;       // chunk (cols [nw*64, nw*64+64))
    const int mbase = mw * 32;
    const int node0 = blockIdx.x * 4;

    // ---- B fill: stage s loads [s][c(4)][n(64)][32k] = 32KB contiguous ----
    auto fill_b = [&](int s) {
        const char* src = (const char*)g_Wt + (size_t)s * 32768;
        const uint32_t dst = bs_u + (uint32_t)(s & 1) * BBUF_BYTES;
        #pragma unroll
        for (int ii = 0; ii < 4; ii++) {
            int idx = tid + ii * THREADS2;          // 0..2047
            int r = idx >> 3, c16 = (idx & 7) * 16;
            cp_async16(dst + r * (B_ST * 4) + c16, src + r * 128 + c16);
        }
        cp_async_commit();
    };

    // ---- prefetch stages 0 and 1 ----
    fill_b(0);
    fill_b(1);

    // ---- A tile fill: plain layout, tf32-rounded (proven) ----
    const float* Asrc = transformed + (size_t)(node0 * MMN) * FF;
    for (int idx = tid; idx < 128 * 64; idx += THREADS2) {
        int r  = idx >> 6;
        int c4 = (idx & 63) * 4;
        float4 v = *(const float4*)(Asrc + (size_t)r * FF + c4);
        float* d = &As[r * A_ST + c4];
        d[0] = __uint_as_float(f2tf32(v.x));
        d[1] = __uint_as_float(f2tf32(v.y));
        d[2] = __uint_as_float(f2tf32(v.z));
        d[3] = __uint_as_float(f2tf32(v.w));
    }
    // ---- O2 bias + attention vector ----
    for (int idx = tid; idx < 4 * FF; idx += THREADS2)
        o2_s[idx] = g_O2[(size_t)(node0 + (idx >> 8)) * FF + (idx & 255)];
    if (tid < FF) a_s[tid] = a_vec[tid];

    float c[2][8][4];                      // 32m x 64n accumulators (full K)
    #pragma unroll
    for (int mt = 0; mt < 2; mt++)
        #pragma unroll
        for (int nt = 0; nt < 8; nt++)
            #pragma unroll
            for (int i = 0; i < 4; i++) c[mt][nt][i] = 0.f;

    for (int s = 0; s < 8; s++) {          // K eighths
        if (s == 7) cp_async_wait<0>(); else cp_async_wait<1>();
        __syncthreads();

        const float* Bq = Bs + (size_t)(s & 1) * BBUF_FLOATS + (size_t)nw * (64 * B_ST);
        const int kbase = s * 32;

        #pragma unroll
        for (int ko = 0; ko < 32; ko += 8) {
            const int k0 = kbase + ko;
            // A: 8 scalar LDS.32 (conflict-free, banks 4g+tg)
            float aA0 = As[(mbase + g)      * A_ST + k0 + tg];
            float aA4 = As[(mbase + g)      * A_ST + k0 + tg + 4];
            float aB0 = As[(mbase + g + 8)  * A_ST + k0 + tg];
            float aB4 = As[(mbase + g + 8)  * A_ST + k0 + tg + 4];
            float aC0 = As[(mbase + g + 16) * A_ST + k0 + tg];
            float aC4 = As[(mbase + g + 16) * A_ST + k0 + tg + 4];
            float aD0 = As[(mbase + g + 24) * A_ST + k0 + tg];
            float aD4 = As[(mbase + g + 24) * A_ST + k0 + tg + 4];

            #pragma unroll
            for (int nt = 0; nt < 8; nt++) {
                // B: LDS.64, interleaved pair (k0+tg, k0+tg+4) at index ko + 2tg
                float2 b = *(const float2*)&Bq[(nt * 8 + g) * B_ST + ko + 2 * tg];
                mma_tf32(c[0][nt], aA0, aB0, aA4, aB4, b.x, b.y);
                mma_tf32(c[1][nt], aC0, aD0, aC4, aD4, b.x, b.y);
            }
        }

        __syncthreads();   // all warps done reading this B buffer
        if (s < 6) fill_b(s + 2);
    }

    // ---- single epilogue: +bias, leaky-relu, dot with a -> e partials ----
    float ep[4] = {0.f, 0.f, 0.f, 0.f};   // rows mbase+{g,g+8,g+16,g+24}
    #pragma unroll
    for (int mt = 0; mt < 2; mt++) {
        #pragma unroll
        for (int nt = 0; nt < 8; nt++) {
            int o = nw * 64 + nt * 8 + 2 * tg;
            float o20 = o2_s[mw * FF + o];
            float o21 = o2_s[mw * FF + o + 1];
            float av0 = a_s[o];
            float av1 = a_s[o + 1];
            float y;
            y = c[mt][nt][0] + o20; y = (y > 0.f) ? y : ALPHA_L * y; ep[mt*2]   += y * av0;
            y = c[mt][nt][1] + o21; y = (y > 0.f) ? y : ALPHA_L * y; ep[mt*2]   += y * av1;
            y = c[mt][nt][2] + o20; y = (y > 0.f) ? y : ALPHA_L * y; ep[mt*2+1] += y * av0;
            y = c[mt][nt][3] + o21; y = (y > 0.f) ? y : ALPHA_L * y; ep[mt*2+1] += y * av1;
        }
    }

    // quad-reduce e partials, publish per chunk
    #pragma unroll
    for (int i = 0; i < 4; i++) {
        ep[i] += __shfl_down_sync(0xffffffffu, ep[i], 2, 4);
        ep[i] += __shfl_down_sync(0xffffffffu, ep[i], 1, 4);
    }
    if (tg == 0) {
        #pragma unroll
        for (int i = 0; i < 4; i++)
            e_sh[nw * 128 + mbase + i * 8 + g] = ep[i];
    }
    __syncthreads();

    // softmax per node (warps 0-3 handle nodes 0-3)
    if (w < 4) {
        float e = e_sh[w * 32 + lane] + e_sh[128 + w * 32 + lane]
                + e_sh[256 + w * 32 + lane] + e_sh[384 + w * 32 + lane];
        float mx = e;
        #pragma unroll
        for (int o = 16; o > 0; o >>= 1)
            mx = fmaxf(mx, __shfl_xor_sync(0xffffffffu, mx, o));
        float p = expf(e - mx);
        float sum = p;
        #pragma unroll
        for (int o = 16; o > 0; o >>= 1)
            sum += __shfl_xor_sync(0xffffffffu, sum, o);
        float att = p / sum;
        att_s[w * 32 + lane] = att;
        out[(size_t)NN * FF + (size_t)(node0 + w) * MMN + lane] = att;
    }
    __syncthreads();

    // h_prime[f] = sum_m att * A (plain smem layout), then ELU
    {
        const int f  = tid & 255;
        const int pr = tid >> 8;       // 0 or 1 -> nodes {0,1} / {2,3}
        #pragma unroll
        for (int t = 0; t < 2; t++) {
            const int nl = pr * 2 + t;
            float acc = 0.f;
            #pragma unroll 8
            for (int m = 0; m < MMN; m++) {
                int r = nl * MMN + m;
                acc = fmaf(att_s[r], As[r * A_ST + f], acc);
            }
            float rres = (acc > 0.f) ? acc : expm1f(acc);
            out[(size_t)(node0 + nl) * FF + f] = rres;
        }
    }
}

// ---------------------------------------------------------------------------
extern "C" void kernel_launch(void* const* d_in, const int* in_sizes, int n_in,
                              void* d_out, int out_size) {
    const float* transformed = (const float*)d_in[0];
    const float* output      = (const float*)d_in[1];
    const float* W           = (const float*)d_in[2];
    const float* a_vec       = (const float*)d_in[3];
    float* out = (float*)d_out;

    const int smem_o2 = (ROWS_PB * A_STRIDE1 + FF * W_STRIDE1) * sizeof(float);
    cudaFuncSetAttribute(o2_gemm_kernel,
                         cudaFuncAttributeMaxDynamicSharedMemorySize, smem_o2);
    cudaFuncSetAttribute(gat_fused3_kernel,
                         cudaFuncAttributeMaxDynamicSharedMemorySize, GAT_SMEM);

    wt_kernel<<<FF, FF>>>(W);
    o2_gemm_kernel<<<NN / ROWS_PB, 256, smem_o2>>>(output, W);
    gat_fused3_kernel<<<NN / 4, THREADS2, GAT_SMEM>>>(transformed, a_vec, out);
}

// round 15
// speedup vs baseline: 1.0015x; 1.0011x over previous
#include <cuda_runtime.h>
#include <math.h>
#include <stdint.h>

// Problem constants
#define NN      16384
#define MMN     32
#define FF      256
#define ALPHA_L 0.2f

// ---------------- scratch ----------------
__device__ float g_O2[(size_t)NN * FF];   // output @ W2 (bias per node per out-feat)
// W1 rearranged: 32 blocks [s(8)][c(4)] of [n_local(64)][k_local(32) interleaved]
__device__ float g_Wt[(size_t)FF * FF];

// ---------------- helpers ----------------
__device__ __forceinline__ uint32_t f2tf32(float x) {
    uint32_t r;
    asm("cvt.rna.tf32.f32 %0, %1;" : "=r"(r) : "f"(x));
    return r;
}

__device__ __forceinline__ uint32_t smem_to_u32(const void* p) {
    uint32_t a;
    asm("{ .reg .u64 t; cvta.to.shared.u64 t, %1; cvt.u32.u64 %0, t; }"
        : "=r"(a) : "l"(p));
    return a;
}

__device__ __forceinline__ void cp_async16(uint32_t dst_smem, const void* src) {
    asm volatile("cp.async.cg.shared.global [%0], [%1], 16;"
                 :: "r"(dst_smem), "l"(src) : "memory");
}
__device__ __forceinline__ void cp_async_commit() {
    asm volatile("cp.async.commit_group;" ::: "memory");
}
template <int N>
__device__ __forceinline__ void cp_async_wait() {
    asm volatile("cp.async.wait_group %0;" :: "n"(N) : "memory");
}

__device__ __forceinline__ void mma_tf32(float c[4],
                                         float a0, float a1, float a2, float a3,
                                         float b0, float b1) {
    asm volatile(
        "mma.sync.aligned.m16n8k8.row.col.f32.tf32.tf32.f32 "
        "{%0,%1,%2,%3}, {%4,%5,%6,%7}, {%8,%9}, {%0,%1,%2,%3};\n"
        : "+f"(c[0]), "+f"(c[1]), "+f"(c[2]), "+f"(c[3])
        : "r"(__float_as_uint(a0)), "r"(__float_as_uint(a1)),
          "r"(__float_as_uint(a2)), "r"(__float_as_uint(a3)),
          "r"(__float_as_uint(b0)), "r"(__float_as_uint(b1)));
}

// ---------------------------------------------------------------------------
// Kernel 0: W1 -> g_Wt, tf32-rounded, [s(8)][c(4)][n(64)][k(32) interleaved]
// interleave within 8-block of k: k -> 2*(k&3) + ((k>>2)&1)
// ---------------------------------------------------------------------------
__global__ void wt_kernel(const float* __restrict__ W) {
    int n = blockIdx.x, k = threadIdx.x;
    int c = n >> 6, nl = n & 63;
    int s = k >> 5, kl = k & 31;
    int pos = (kl & ~7) + 2 * (kl & 3) + ((kl >> 2) & 1);
    size_t dst = ((size_t)((s * 4 + c) * 64 + nl)) * 32 + pos;
    g_Wt[dst] = __uint_as_float(f2tf32(W[(size_t)k * FF + n]));
}

// ---------------------------------------------------------------------------
// Kernel 1: O2 = output @ W2  (round-1 proven kernel, unchanged, 256 thr)
// ---------------------------------------------------------------------------
#define ROWS_PB   128
#define A_STRIDE1 260
#define W_STRIDE1 72

__global__ void __launch_bounds__(256, 1)
o2_gemm_kernel(const float* __restrict__ output, const float* __restrict__ W) {
    extern __shared__ float smemf[];
    float* As = smemf;
    float* Ws = As + ROWS_PB * A_STRIDE1;

    const int tid  = threadIdx.x;
    const int w    = tid >> 5;
    const int lane = tid & 31;
    const int g    = lane >> 2;
    const int tg   = lane & 3;
    const int mbase = w * 16;
    const int row0 = blockIdx.x * ROWS_PB;

    for (int idx = tid; idx < ROWS_PB * (FF / 4); idx += 256) {
        int r  = idx >> 6;
        int c4 = (idx & 63) * 4;
        float4 v = *(const float4*)(output + (size_t)(row0 + r) * FF + c4);
        float* d = &As[r * A_STRIDE1 + c4];
        d[0] = __uint_as_float(f2tf32(v.x));
        d[1] = __uint_as_float(f2tf32(v.y));
        d[2] = __uint_as_float(f2tf32(v.z));
        d[3] = __uint_as_float(f2tf32(v.w));
    }

    for (int nc = 0; nc < 4; nc++) {
        __syncthreads();
        for (int idx = tid; idx < FF * 16; idx += 256) {
            int k = idx >> 4;
            int j = (idx & 15) * 4;
            float4 v = *(const float4*)(W + (size_t)(FF + k) * FF + nc * 64 + j);
            float* d = &Ws[k * W_STRIDE1 + j];
            d[0] = __uint_as_float(f2tf32(v.x));
            d[1] = __uint_as_float(f2tf32(v.y));
            d[2] = __uint_as_float(f2tf32(v.z));
            d[3] = __uint_as_float(f2tf32(v.w));
        }
        __syncthreads();

        float c[8][4];
        #pragma unroll
        for (int n0 = 0; n0 < 8; n0++)
            #pragma unroll
            for (int i = 0; i < 4; i++) c[n0][i] = 0.f;

        #pragma unroll 4
        for (int k0 = 0; k0 < FF; k0 += 8) {
            float a0 = As[(mbase + g)     * A_STRIDE1 + k0 + tg];
            float a1 = As[(mbase + g + 8) * A_STRIDE1 + k0 + tg];
            float a2 = As[(mbase + g)     * A_STRIDE1 + k0 + tg + 4];
            float a3 = As[(mbase + g + 8) * A_STRIDE1 + k0 + tg + 4];
            #pragma unroll
            for (int n0 = 0; n0 < 8; n0++) {
                float b0 = Ws[(k0 + tg)     * W_STRIDE1 + n0 * 8 + g];
                float b1 = Ws[(k0 + tg + 4) * W_STRIDE1 + n0 * 8 + g];
                mma_tf32(c[n0], a0, a1, a2, a3, b0, b1);
            }
        }

        #pragma unroll
        for (int n0 = 0; n0 < 8; n0++) {
            int col = nc * 64 + n0 * 8 + tg * 2;
            size_t rA = (size_t)(row0 + mbase + g) * FF + col;
            size_t rB = (size_t)(row0 + mbase + g + 8) * FF + col;
            g_O2[rA]     = c[n0][0];
            g_O2[rA + 1] = c[n0][1];
            g_O2[rB]     = c[n0][2];
            g_O2[rB + 1] = c[n0][3];
        }
    }
}

// ---------------------------------------------------------------------------
// Kernel 2: fused GAT. 512 threads / 16 warps, warp grid 4m x 4chunk.
//   Warp (mw, nw) computes rows [mw*32,mw*32+32) x cols [nw*64,nw*64+64).
//   K staged in eighths of 32 for ALL 4 chunks, double-buffered cp.async.
//   Accumulators persist across all K -> single epilogue.
//   A smem: 128 x 260 fp32 (tf32-rounded), plain layout (proven).
//   B smem: 2 dbuf x [4 chunks][64 n][k 32+8 pad], k-pair interleaved.
// ---------------------------------------------------------------------------
#define THREADS2 512
#define A_ST 260
#define B_ST 40
#define A_BYTES    (128 * A_ST * 4)       // 133120
#define BBUF_FLOATS (4 * 64 * B_ST)       // 10240 floats
#define BBUF_BYTES (BBUF_FLOATS * 4)      // 40960
#define GAT_SMEM   (A_BYTES + 2 * BBUF_BYTES + 4 * FF * 4 + FF * 4 + 128 * 4 + 4 * 128 * 4)

__global__ void __launch_bounds__(THREADS2, 1)
gat_fused3_kernel(const float* __restrict__ transformed,
                  const float* __restrict__ a_vec,
                  float* __restrict__ out) {
    extern __shared__ char smem[];
    float* As    = (float*)smem;                               // 128 x 260
    float* Bs    = (float*)(smem + A_BYTES);                   // 2 x [4][64][40]
    float* o2_s  = (float*)(smem + A_BYTES + 2 * BBUF_BYTES);  // 4 x 256
    float* a_s   = o2_s + 4 * FF;                              // 256
    float* att_s = a_s + FF;                                   // 128
    float* e_sh  = att_s + 128;                                // 4 x 128

    const uint32_t bs_u = smem_to_u32(Bs);

    const int tid  = threadIdx.x;
    const int w    = tid >> 5;
    const int lane = tid & 31;
    const int g    = lane >> 2;
    const int tg   = lane & 3;
    const int mw   = w & 3;        // m-warp: rows [mw*32, mw*32+32) -> node mw
    const int nw   = w >> 2;       // chunk (cols [nw*64, nw*64+64))
    const int mbase = mw * 32;
    const int node0 = blockIdx.x * 4;

    // ---- B fill: stage s loads [s][c(4)][n(64)][32k] = 32KB contiguous ----
    auto fill_b = [&](int s) {
        const char* src = (const char*)g_Wt + (size_t)s * 32768;
        const uint32_t dst = bs_u + (uint32_t)(s & 1) * BBUF_BYTES;
        #pragma unroll
        for (int ii = 0; ii < 4; ii++) {
            int idx = tid + ii * THREADS2;          // 0..2047
            int r = idx >> 3, c16 = (idx & 7) * 16;
            cp_async16(dst + r * (B_ST * 4) + c16, src + r * 128 + c16);
        }
        cp_async_commit();
    };

    // ---- prefetch stages 0 and 1 ----
    fill_b(0);
    fill_b(1);

    // ---- A tile fill: plain layout, tf32-rounded (proven) ----
    const float* Asrc = transformed + (size_t)(node0 * MMN) * FF;
    for (int idx = tid; idx < 128 * 64; idx += THREADS2) {
        int r  = idx >> 6;
        int c4 = (idx & 63) * 4;
        float4 v = *(const float4*)(Asrc + (size_t)r * FF + c4);
        float* d = &As[r * A_ST + c4];
        d[0] = __uint_as_float(f2tf32(v.x));
        d[1] = __uint_as_float(f2tf32(v.y));
        d[2] = __uint_as_float(f2tf32(v.z));
        d[3] = __uint_as_float(f2tf32(v.w));
    }
    // ---- O2 bias + attention vector ----
    for (int idx = tid; idx < 4 * FF; idx += THREADS2)
        o2_s[idx] = g_O2[(size_t)(node0 + (idx >> 8)) * FF + (idx & 255)];
    if (tid < FF) a_s[tid] = a_vec[tid];

    float c[2][8][4];                      // 32m x 64n accumulators (full K)
    #pragma unroll
    for (int mt = 0; mt < 2; mt++)
        #pragma unroll
        for (int nt = 0; nt < 8; nt++)
            #pragma unroll
            for (int i = 0; i < 4; i++) c[mt][nt][i] = 0.f;

    for (int s = 0; s < 8; s++) {          // K eighths
        if (s == 7) cp_async_wait<0>(); else cp_async_wait<1>();
        __syncthreads();

        const float* Bq = Bs + (size_t)(s & 1) * BBUF_FLOATS + (size_t)nw * (64 * B_ST);
        const int kbase = s * 32;

        #pragma unroll
        for (int ko = 0; ko < 32; ko += 8) {
            const int k0 = kbase + ko;
            // A: 8 scalar LDS.32 (conflict-free, banks 4g+tg)
            float aA0 = As[(mbase + g)      * A_ST + k0 + tg];
            float aA4 = As[(mbase + g)      * A_ST + k0 + tg + 4];
            float aB0 = As[(mbase + g + 8)  * A_ST + k0 + tg];
            float aB4 = As[(mbase + g + 8)  * A_ST + k0 + tg + 4];
            float aC0 = As[(mbase + g + 16) * A_ST + k0 + tg];
            float aC4 = As[(mbase + g + 16) * A_ST + k0 + tg + 4];
            float aD0 = As[(mbase + g + 24) * A_ST + k0 + tg];
            float aD4 = As[(mbase + g + 24) * A_ST + k0 + tg + 4];

            #pragma unroll
            for (int nt = 0; nt < 8; nt++) {
                // B: LDS.64, interleaved pair (k0+tg, k0+tg+4) at index ko + 2tg
                float2 b = *(const float2*)&Bq[(nt * 8 + g) * B_ST + ko + 2 * tg];
                mma_tf32(c[0][nt], aA0, aB0, aA4, aB4, b.x, b.y);
                mma_tf32(c[1][nt], aC0, aD0, aC4, aD4, b.x, b.y);
            }
        }

        __syncthreads();   // all warps done reading this B buffer
        if (s < 6) fill_b(s + 2);
    }

    // ---- single epilogue: +bias, leaky-relu, dot with a -> e partials ----
    float ep[4] = {0.f, 0.f, 0.f, 0.f};   // rows mbase+{g,g+8,g+16,g+24}
    #pragma unroll
    for (int mt = 0; mt < 2; mt++) {
        #pragma unroll
        for (int nt = 0; nt < 8; nt++) {
            int o = nw * 64 + nt * 8 + 2 * tg;
            float o20 = o2_s[mw * FF + o];
            float o21 = o2_s[mw * FF + o + 1];
            float av0 = a_s[o];
            float av1 = a_s[o + 1];
            float y;
            y = c[mt][nt][0] + o20; y = (y > 0.f) ? y : ALPHA_L * y; ep[mt*2]   += y * av0;
            y = c[mt][nt][1] + o21; y = (y > 0.f) ? y : ALPHA_L * y; ep[mt*2]   += y * av1;
            y = c[mt][nt][2] + o20; y = (y > 0.f) ? y : ALPHA_L * y; ep[mt*2+1] += y * av0;
            y = c[mt][nt][3] + o21; y = (y > 0.f) ? y : ALPHA_L * y; ep[mt*2+1] += y * av1;
        }
    }

    // quad-reduce e partials, publish per chunk
    #pragma unroll
    for (int i = 0; i < 4; i++) {
        ep[i] += __shfl_down_sync(0xffffffffu, ep[i], 2, 4);
        ep[i] += __shfl_down_sync(0xffffffffu, ep[i], 1, 4);
    }
    if (tg == 0) {
        #pragma unroll
        for (int i = 0; i < 4; i++)
            e_sh[nw * 128 + mbase + i * 8 + g] = ep[i];
    }
    __syncthreads();

    // softmax per node (warps 0-3 handle nodes 0-3)
    if (w < 4) {
        float e = e_sh[w * 32 + lane] + e_sh[128 + w * 32 + lane]
                + e_sh[256 + w * 32 + lane] + e_sh[384 + w * 32 + lane];
        float mx = e;
        #pragma unroll
        for (int o = 16; o > 0; o >>= 1)
            mx = fmaxf(mx, __shfl_xor_sync(0xffffffffu, mx, o));
        float p = expf(e - mx);
        float sum = p;
        #pragma unroll
        for (int o = 16; o > 0; o >>= 1)
            sum += __shfl_xor_sync(0xffffffffu, sum, o);
        float att = p / sum;
        att_s[w * 32 + lane] = att;
        out[(size_t)NN * FF + (size_t)(node0 + w) * MMN + lane] = att;
    }
    __syncthreads();

    // h_prime[f] = sum_m att * A (plain smem layout), then ELU
    {
        const int f  = tid & 255;
        const int pr = tid >> 8;       // 0 or 1 -> nodes {0,1} / {2,3}
        #pragma unroll
        for (int t = 0; t < 2; t++) {
            const int nl = pr * 2 + t;
            float acc = 0.f;
            #pragma unroll 8
            for (int m = 0; m < MMN; m++) {
                int r = nl * MMN + m;
                acc = fmaf(att_s[r], As[r * A_ST + f], acc);
            }
            float rres = (acc > 0.f) ? acc : expm1f(acc);
            out[(size_t)(node0 + nl) * FF + f] = rres;
        }
    }
}

// ---------------------------------------------------------------------------
extern "C" void kernel_launch(void* const* d_in, const int* in_sizes, int n_in,
                              void* d_out, int out_size) {
    const float* transformed = (const float*)d_in[0];
    const float* output      = (const float*)d_in[1];
    const float* W           = (const float*)d_in[2];
    const float* a_vec       = (const float*)d_in[3];
    float* out = (float*)d_out;

    const int smem_o2 = (ROWS_PB * A_STRIDE1 + FF * W_STRIDE1) * sizeof(float);
    cudaFuncSetAttribute(o2_gemm_kernel,
                         cudaFuncAttributeMaxDynamicSharedMemorySize, smem_o2);
    cudaFuncSetAttribute(gat_fused3_kernel,
                         cudaFuncAttributeMaxDynamicSharedMemorySize, GAT_SMEM);

    wt_kernel<<<FF, FF>>>(W);
    o2_gemm_kernel<<<NN / ROWS_PB, 256, smem_o2>>>(output, W);
    gat_fused3_kernel<<<NN / 4, THREADS2, GAT_SMEM>>>(transformed, a_vec, out);
}